// round 8
// baseline (speedup 1.0000x reference)
#include <cuda_runtime.h>
#include <cuda_bf16.h>
#include <math_constants.h>

// Problem constants
#define BATCH 16
#define SEQ   4096
#define EMB   2048
#define WIN   64

#define ROWS_PER_GROUP 8
#define NGROUPS (BATCH * SEQ / ROWS_PER_GROUP)   // 8192
#define NWIN (SEQ - WIN + 1)                     // 4033

// Scratch (static device arrays: allocation-free, zero-initialized at load)
__device__ float        g_scores[BATCH * SEQ];
__device__ unsigned int g_cnt;   // blocks arrived
__device__ unsigned int g_fin;   // finishers done (for reset)

// ---------------------------------------------------------------------------
// Persistent fused kernel (grid = one resident wave):
//  Phase A: grid-stride over 8192 row-groups; per warp: masked-skip dot(x,W)+b
//  Arrival: one fence + counter add per block
//  Phase B: blocks 0..15 spin until all arrived, then batch b's window-max.
// ---------------------------------------------------------------------------
__global__ __launch_bounds__(256) void fused_kernel(
    const float* __restrict__ x,
    const int*   __restrict__ mask,   // bool mask coerced to int32 by harness
    const float* __restrict__ W,
    const float* __restrict__ bias,
    float*       __restrict__ out)
{
    __shared__ float sbuf[SEQ];   // 16 KB: W lives in [0..EMB) during phase A,
                                  // phase B restages the batch's 4096 scores
    __shared__ float red[8];

    const int tid  = threadIdx.x;
    const int wid  = tid >> 5;
    const int lane = tid & 31;

    // Stage W into shared (first 2048 floats of sbuf)
    for (int i = tid; i < EMB; i += 256)
        sbuf[i] = W[i];
    __syncthreads();

    const float4* __restrict__ wr = reinterpret_cast<const float4*>(sbuf);
    const float  bval = bias[0];

    // ---------------- Phase A: stream x, write scores -----------------------
    for (int g = blockIdx.x; g < NGROUPS; g += gridDim.x) {
        const int row = g * ROWS_PER_GROUP + wid;

        // Mask gate: skip the 8KB row read when masked out (~10% of rows)
        if (mask[row] == 0) {
            if (lane == 0) g_scores[row] = 0.0f;
            continue;
        }

        const float4* __restrict__ xr =
            reinterpret_cast<const float4*>(x + (size_t)row * EMB);

        float acc = 0.0f;
        #pragma unroll
        for (int h = 0; h < 2; h++) {
            float4 a[8];
            #pragma unroll
            for (int j = 0; j < 8; j++)
                a[j] = __ldcs(&xr[lane + (h * 8 + j) * 32]);
            #pragma unroll
            for (int j = 0; j < 8; j++) {
                float4 w = wr[lane + (h * 8 + j) * 32];
                acc = fmaf(a[j].x, w.x, acc);
                acc = fmaf(a[j].y, w.y, acc);
                acc = fmaf(a[j].z, w.z, acc);
                acc = fmaf(a[j].w, w.w, acc);
            }
        }

        #pragma unroll
        for (int o = 16; o > 0; o >>= 1)
            acc += __shfl_xor_sync(0xffffffffu, acc, o);

        if (lane == 0)
            g_scores[row] = acc + bval;
    }

    // ---------------- Arrival: one fence + add per block --------------------
    __syncthreads();
    if (tid == 0) {
        __threadfence();               // publish this block's score stores
        atomicAdd(&g_cnt, 1u);
    }

    if (blockIdx.x >= BATCH) return;   // non-finishers exit

    // ---------------- Phase B: finisher for batch b = blockIdx.x ------------
    const int b = blockIdx.x;

    if (tid == 0) {
        // Spin until every block has arrived (all blocks co-resident: safe)
        while (atomicAdd(&g_cnt, 0u) < gridDim.x)
            __nanosleep(64);
        __threadfence();               // acquire: order spin before score reads
    }
    __syncthreads();

    // Stage this batch's 4096 scores (L2-hot) into shared, bypassing L1
    {
        const float4* src = reinterpret_cast<const float4*>(g_scores + b * SEQ);
        float4*       dst = reinterpret_cast<float4*>(sbuf);
        #pragma unroll
        for (int i = 0; i < SEQ / 4 / 256; i++)      // 4 iters
            dst[tid + i * 256] = __ldcg(&src[tid + i * 256]);
    }
    __syncthreads();

    // Thread t covers window starts 16t .. 16t+15 via rolling sum
    const int start0 = tid * 16;
    float best = -CUDART_INF_F;
    if (start0 < NWIN) {
        const float4* sv = reinterpret_cast<const float4*>(sbuf) + tid * 4;
        float sum = 0.0f;
        #pragma unroll
        for (int k = 0; k < WIN / 4; k++) {
            float4 v = sv[k];
            sum += (v.x + v.y) + (v.z + v.w);
        }
        best = sum;
        #pragma unroll
        for (int j = 1; j < 16; j++) {
            int i = start0 + j;
            if (i < NWIN) {
                sum += sbuf[i + WIN - 1] - sbuf[i - 1];
                best = fmaxf(best, sum);
            }
        }
    }

    // Block max reduce (8 warps)
    #pragma unroll
    for (int o = 16; o > 0; o >>= 1)
        best = fmaxf(best, __shfl_xor_sync(0xffffffffu, best, o));
    if (lane == 0) red[wid] = best;
    __syncthreads();

    if (tid == 0) {
        float v = red[0];
        #pragma unroll
        for (int i = 1; i < 8; i++)
            v = fmaxf(v, red[i]);
        out[b] = v * (1.0f / (float)WIN);

        // Reset counters for the next graph replay: last finisher cleans up.
        unsigned int r = atomicAdd(&g_fin, 1u);
        if (r == BATCH - 1) {
            atomicExch(&g_cnt, 0u);
            atomicExch(&g_fin, 0u);
        }
    }
}

// ---------------------------------------------------------------------------
// Launch: single persistent kernel, grid = exactly one resident wave
// ---------------------------------------------------------------------------
extern "C" void kernel_launch(void* const* d_in, const int* in_sizes, int n_in,
                              void* d_out, int out_size)
{
    const float* x    = (const float*)d_in[0];
    const int*   mask = (const int*)d_in[1];
    const float* W    = (const float*)d_in[2];
    const float* bias = (const float*)d_in[3];
    float*       out  = (float*)d_out;

    int numSMs = 0, occ = 0;
    cudaDeviceGetAttribute(&numSMs, cudaDevAttrMultiProcessorCount, 0);
    cudaOccupancyMaxActiveBlocksPerMultiprocessor(&occ, fused_kernel, 256, 0);
    if (occ < 1) occ = 1;

    int grid = numSMs * occ;           // guaranteed co-resident
    if (grid > NGROUPS) grid = NGROUPS;
    if (grid < BATCH)   grid = BATCH;  // need >=16 finishers (can't happen)

    fused_kernel<<<grid, 256>>>(x, mask, W, bias, out);
}

// round 9
// speedup vs baseline: 1.0407x; 1.0407x over previous
#include <cuda_runtime.h>
#include <cuda_bf16.h>
#include <math_constants.h>

// Problem constants
#define BATCH 16
#define SEQ   4096
#define EMB   2048
#define WIN   64
#define NWIN  (SEQ - WIN + 1)   // 4033

// Scratch for per-token scores (static device array: allocation-free)
__device__ float g_scores[BATCH * SEQ];

// ---------------------------------------------------------------------------
// Kernel 1 (unchanged from R7 — at HBM roofline):
// s[b,t] = mask[b,t] ? dot(x[b,t,:], W) + bias : 0
// One warp per row, masked rows skip the 8KB read, streaming loads MLP=8.
// ---------------------------------------------------------------------------
__global__ __launch_bounds__(256) void score_kernel(
    const float* __restrict__ x,
    const int*   __restrict__ mask,   // bool mask coerced to int32 by harness
    const float* __restrict__ W,
    const float* __restrict__ bias)
{
    __shared__ float sW[EMB];
    for (int i = threadIdx.x; i < EMB; i += blockDim.x)
        sW[i] = W[i];
    __syncthreads();

    const int warpsPerBlock = blockDim.x >> 5;
    const int warp = blockIdx.x * warpsPerBlock + (threadIdx.x >> 5);
    const int lane = threadIdx.x & 31;
    if (warp >= BATCH * SEQ) return;

    const int m = mask[warp];
    if (m == 0) {
        if (lane == 0) g_scores[warp] = 0.0f;
        return;
    }

    const float4* __restrict__ xr = reinterpret_cast<const float4*>(x + (size_t)warp * EMB);
    const float4* __restrict__ wr = reinterpret_cast<const float4*>(sW);

    float acc = 0.0f;
    #pragma unroll
    for (int h = 0; h < 2; h++) {
        float4 a[8];
        #pragma unroll
        for (int j = 0; j < 8; j++)
            a[j] = __ldcs(&xr[lane + (h * 8 + j) * 32]);
        #pragma unroll
        for (int j = 0; j < 8; j++) {
            float4 w = wr[lane + (h * 8 + j) * 32];
            acc = fmaf(a[j].x, w.x, acc);
            acc = fmaf(a[j].y, w.y, acc);
            acc = fmaf(a[j].z, w.z, acc);
            acc = fmaf(a[j].w, w.w, acc);
        }
    }

    #pragma unroll
    for (int o = 16; o > 0; o >>= 1)
        acc += __shfl_xor_sync(0xffffffffu, acc, o);

    if (lane == 0)
        g_scores[warp] = acc + bias[0];
}

// ---------------------------------------------------------------------------
// Kernel 2: block-wide prefix scan (cumsum), then window sums as cs diffs.
// One block (1024 threads) per batch; each thread owns 4 elements / 4 windows.
// ---------------------------------------------------------------------------
__global__ __launch_bounds__(1024) void window_max_kernel(float* __restrict__ out)
{
    __shared__ float cs[SEQ];       // inclusive prefix sums
    __shared__ float wsum[32];      // per-warp totals
    __shared__ float red[32];

    const int b    = blockIdx.x;
    const int tid  = threadIdx.x;
    const int lane = tid & 31;
    const int wid  = tid >> 5;

    // PDL dependency gate (prelude/ramp overlaps primary's tail)
    cudaGridDependencySynchronize();

    // Load this thread's 4 scores
    float4 v = reinterpret_cast<const float4*>(g_scores + b * SEQ)[tid];

    // Thread-local inclusive prefixes
    float p0 = v.x;
    float p1 = p0 + v.y;
    float p2 = p1 + v.z;
    float p3 = p2 + v.w;

    // Warp inclusive scan of thread totals (p3)
    float t = p3;
    #pragma unroll
    for (int o = 1; o < 32; o <<= 1) {
        float u = __shfl_up_sync(0xffffffffu, t, o);
        if (lane >= o) t += u;
    }
    // exclusive offset within warp
    float warpExcl = t - p3;
    if (lane == 31) wsum[wid] = t;   // warp total
    __syncthreads();

    // Scan the 32 warp totals in warp 0
    if (wid == 0) {
        float wt = wsum[lane];
        #pragma unroll
        for (int o = 1; o < 32; o <<= 1) {
            float u = __shfl_up_sync(0xffffffffu, wt, o);
            if (lane >= o) wt += u;
        }
        wsum[lane] = wt - wsum[lane];   // exclusive warp offsets
    }
    __syncthreads();

    const float base = wsum[wid] + warpExcl;

    // Write inclusive prefix sums
    float4 c;
    c.x = base + p0;
    c.y = base + p1;
    c.z = base + p2;
    c.w = base + p3;
    reinterpret_cast<float4*>(cs)[tid] = c;
    __syncthreads();

    // Window sums: w(i) = cs[i+WIN-1] - (i>0 ? cs[i-1] : 0), i in 4t..4t+3
    const int i0 = tid * 4;
    float best = -CUDART_INF_F;
    #pragma unroll
    for (int j = 0; j < 4; j++) {
        int i = i0 + j;
        if (i < NWIN) {
            float hi = cs[i + WIN - 1];
            float lo = (i > 0) ? cs[i - 1] : 0.0f;
            best = fmaxf(best, hi - lo);
        }
    }

    // Block max reduce
    #pragma unroll
    for (int o = 16; o > 0; o >>= 1)
        best = fmaxf(best, __shfl_xor_sync(0xffffffffu, best, o));
    if (lane == 0) red[wid] = best;
    __syncthreads();
    if (tid < 32) {
        float m = red[tid];
        #pragma unroll
        for (int o = 16; o > 0; o >>= 1)
            m = fmaxf(m, __shfl_xor_sync(0xffffffffu, m, o));
        if (tid == 0)
            out[b] = m * (1.0f / (float)WIN);
    }
}

// ---------------------------------------------------------------------------
// Launch: kernel 1 normally, kernel 2 via PDL
// ---------------------------------------------------------------------------
extern "C" void kernel_launch(void* const* d_in, const int* in_sizes, int n_in,
                              void* d_out, int out_size)
{
    const float* x    = (const float*)d_in[0];
    const int*   mask = (const int*)d_in[1];
    const float* W    = (const float*)d_in[2];
    const float* bias = (const float*)d_in[3];
    float*       out  = (float*)d_out;

    const int totalRows = BATCH * SEQ;               // 65536
    const int warpsPerBlock = 256 / 32;              // 8
    const int grid1 = (totalRows + warpsPerBlock - 1) / warpsPerBlock; // 8192
    score_kernel<<<grid1, 256>>>(x, mask, W, bias);

    cudaLaunchConfig_t cfg = {};
    cfg.gridDim  = dim3(BATCH, 1, 1);
    cfg.blockDim = dim3(1024, 1, 1);
    cfg.dynamicSmemBytes = 0;
    cfg.stream = 0;
    cudaLaunchAttribute attrs[1];
    attrs[0].id = cudaLaunchAttributeProgrammaticStreamSerialization;
    attrs[0].val.programmaticStreamSerializationAllowed = 1;
    cfg.attrs = attrs;
    cfg.numAttrs = 1;
    cudaLaunchKernelEx(&cfg, window_max_kernel, out);
}